// round 14
// baseline (speedup 1.0000x reference)
#include <cuda_runtime.h>
#include <math.h>
#include <stdint.h>

#define N_PTS 8192
#define D_DIM 256
#define NUM_CLS 64
#define EPSF  1e-10f
#define LOG2E 1.4426950408889634f

#define BTI 128                   // tile rows
#define BTJ 64                    // tile cols
#define CE 128                    // K chunk in int8 elems = 128 B per row
#define ROWB 144                  // padded row stride in bytes
#define STAGE_ROWS 192            // A rows 0-127, B rows 128-191
#define STAGE_BYTES (STAGE_ROWS * ROWB)
#define AUX_OFF (2 * STAGE_BYTES)
#define SMEM_TOTAL (AUX_OFF + (3 * 128 + 3 * 64) * 4)
#define N_CTAS_T 4160             // sum over bi<64 of (128 - 2*bi)
#define GRID_P 296                // persistent CTAs (2 per SM x 148)

__device__ float4   g_aux[N_PTS];           // {b, rk, cls(bits), 0}
__device__ float    g_pos[N_PTS];
__device__ float    g_neg[N_PTS];
__device__ int      g_work;
__device__ int      g_done;
__device__ uint32_t g_q8[N_PTS * (D_DIM / 4)];   // packed int8 rows (256B)

static __device__ __forceinline__ uint32_t smem_u32(const void* p) {
    uint32_t a;
    asm("{ .reg .u64 t; cvta.to.shared.u64 t, %1; cvt.u32.u64 %0, t; }"
        : "=r"(a) : "l"(p));
    return a;
}
static __device__ __forceinline__ void cp16(uint32_t dst, const void* src) {
    asm volatile("cp.async.cg.shared.global [%0], [%1], 16;"
                 :: "r"(dst), "l"(src) : "memory");
}
#define CP_COMMIT() asm volatile("cp.async.commit_group;" ::: "memory")
#define CP_WAIT0()  asm volatile("cp.async.wait_group 0;" ::: "memory")

static __device__ __forceinline__ void ldsm4(uint32_t* r, uint32_t addr) {
    asm volatile("ldmatrix.sync.aligned.m8n8.x4.shared.b16 {%0,%1,%2,%3}, [%4];"
                 : "=r"(r[0]), "=r"(r[1]), "=r"(r[2]), "=r"(r[3]) : "r"(addr));
}
static __device__ __forceinline__ void mma_s8(int* c, const uint32_t* a,
                                              const uint32_t* b) {
    asm volatile(
        "mma.sync.aligned.m16n8k32.row.col.s32.s8.s8.s32 "
        "{%0,%1,%2,%3}, {%4,%5,%6,%7}, {%8,%9}, {%0,%1,%2,%3};"
        : "+r"(c[0]), "+r"(c[1]), "+r"(c[2]), "+r"(c[3])
        : "r"(a[0]), "r"(a[1]), "r"(a[2]), "r"(a[3]), "r"(b[0]), "r"(b[1]));
}
static __device__ __forceinline__ uint32_t pack4(float4 v, float s) {
    int q0 = __float2int_rn(v.x * s), q1 = __float2int_rn(v.y * s);
    int q2 = __float2int_rn(v.z * s), q3 = __float2int_rn(v.w * s);
    return (uint32_t)(q0 & 255) | ((uint32_t)(q1 & 255) << 8) |
           ((uint32_t)(q2 & 255) << 16) | ((uint32_t)(q3 & 255) << 24);
}
// strip-triangle decode: tiles (bi, bj) with bj in [2*bi, 128)
// cum(bi) = bi * (129 - bi)
static __device__ __forceinline__ void decode_tile(int t, int& bi, int& bj) {
    int b = (int)((129.0f - sqrtf(16641.0f - 4.0f * (float)t)) * 0.5f);
    while ((b + 1) * (129 - (b + 1)) <= t) ++b;
    while (b * (129 - b) > t) --b;
    bi = b; bj = 2 * b + (t - b * (129 - b));
}

// ---------------------------------------------------------------------------
// Kernel 1: per-row norm + int8 quantization + temperature-folded constants
// + dtype detect + class load + counter/accumulator reset. One warp per row.
// ---------------------------------------------------------------------------
__global__ void prep_kernel(const float* __restrict__ pred,
                            const void* __restrict__ tgt,
                            const float* __restrict__ tempPtr) {
    int warp = (blockIdx.x * blockDim.x + threadIdx.x) >> 5;
    int lane = threadIdx.x & 31;
    if (warp >= N_PTS) return;

    // dtype scan on first 1KB (L2-resident): int32 data shows values >= 64
    const long long* t64 = (const long long*)tgt;
    int bad = 0;
#pragma unroll
    for (int q = 0; q < 4; ++q) {
        long long v = t64[lane + 32 * q];
        bad |= (v < 0 || v >= (long long)NUM_CLS);
    }
    bool is64 = (__ballot_sync(0xffffffffu, bad) == 0u);

    const float4* row = (const float4*)(pred + (size_t)warp * D_DIM);
    float4 v0 = row[lane], v1 = row[lane + 32];
    float s = v0.x * v0.x + v0.y * v0.y + v0.z * v0.z + v0.w * v0.w
            + v1.x * v1.x + v1.y * v1.y + v1.z * v1.z + v1.w * v1.w;
    float m = fmaxf(fmaxf(fmaxf(fabsf(v0.x), fabsf(v0.y)),
                          fmaxf(fabsf(v0.z), fabsf(v0.w))),
                    fmaxf(fmaxf(fabsf(v1.x), fabsf(v1.y)),
                          fmaxf(fabsf(v1.z), fabsf(v1.w))));
#pragma unroll
    for (int o = 16; o; o >>= 1) {
        s += __shfl_xor_sync(0xffffffffu, s, o);
        m = fmaxf(m, __shfl_xor_sync(0xffffffffu, m, o));
    }
    float scale = 127.0f / m;                    // m > 0 for gaussian data
    g_q8[warp * 64 + lane]      = pack4(v0, scale);
    g_q8[warp * 64 + 32 + lane] = pack4(v1, scale);
    if (lane == 0) {
        float invT = 1.0f / tempPtr[0];
        float rs   = m * (1.0f / 127.0f);
        int cls    = is64 ? (int)t64[warp] : ((const int*)tgt)[warp];
        g_aux[warp] = make_float4(-s * invT * LOG2E,
                                  rs * sqrtf(2.0f * invT * LOG2E),
                                  __int_as_float(cls), 0.f);
        g_pos[warp] = 0.f;
        g_neg[warp] = 0.f;
        if (warp == 0) { g_work = 0; g_done = 0; }
    }
}

// ---------------------------------------------------------------------------
// Kernel 2: persistent int8 m16n8k32 Gram, 128x64 strip tiles, 16 warps of
// 32x16 (acc=16 regs -> 64 regs/thread -> 8 warps/SMSP), fused epilogue.
// ---------------------------------------------------------------------------
__global__ __launch_bounds__(512, 2)
void tile_kernel(float* __restrict__ out) {
    extern __shared__ char smc[];
    uint32_t sbase = smem_u32(smc);
    float* bR  = (float*)(smc + AUX_OFF);     // [128]
    float* rkR = bR + 128;
    int*   clR = (int*)(rkR + 128);
    float* bC  = (float*)(clR + 128);         // [64]
    float* rkC = bC + 64;
    int*   clC = (int*)(rkC + 64);
    __shared__ int s_cur, s_nxt, s_fin;

    int tid  = threadIdx.x;
    int lane = tid & 31, wid = tid >> 5;
    int wm = wid & 3, wn = wid >> 2;          // 4 x 4 warp grid
    int R0 = wm * 32, C0 = wn * 16;
    int gq = lane >> 2, tq = lane & 3;

    int seg = tid & 7;                        // cp.async 16B segment
    int rbase = tid >> 3;                     // 0..63

    auto prefetch = [&](int i0, int j0) {
#pragma unroll
        for (int st = 0; st < 2; ++st) {
            uint32_t sdst = sbase + (uint32_t)(st * STAGE_BYTES) + seg * 16u;
            int k0 = st * CE;
#pragma unroll
            for (int i = 0; i < 3; ++i) {
                int row = rbase + 64 * i;     // 0..191
                const char* src = (row < 128)
                    ? (const char*)g_q8 + (size_t)(i0 + row) * D_DIM
                    : (const char*)g_q8 + (size_t)(j0 + row - 128) * D_DIM;
                cp16(sdst + (uint32_t)row * ROWB, src + k0 + seg * 16);
            }
            CP_COMMIT();
        }
    };

    uint32_t offA = (uint32_t)((R0 + (lane & 15)) * ROWB + (lane >> 4) * 16);
    uint32_t offB = (uint32_t)((128 + C0 + (lane >> 4) * 8 + (lane & 7)) * ROWB
                               + ((lane >> 3) & 1) * 16);

    if (tid == 0) s_cur = atomicAdd(&g_work, 1);
    __syncthreads();
    int tile = s_cur, bi = 0, bj = 0;
    if (tile < N_CTAS_T) {
        decode_tile(tile, bi, bj);
        prefetch(bi * BTI, bj * BTJ);
    }

    while (tile < N_CTAS_T) {
        int i0 = bi * BTI, j0 = bj * BTJ;
        bool diag = ((bj >> 1) == bi);        // strip contains the diagonal

        if (tid == 0) s_nxt = atomicAdd(&g_work, 1);
        if (tid < 128) {
            float4 a = g_aux[i0 + tid];
            bR[tid] = a.x; rkR[tid] = a.y; clR[tid] = __float_as_int(a.z);
        } else if (tid < 192) {
            float4 b = g_aux[j0 + tid - 128];
            bC[tid - 128] = b.x; rkC[tid - 128] = b.y;
            clC[tid - 128] = __float_as_int(b.z);
        }

        int acc[2][2][4];
#pragma unroll
        for (int mi = 0; mi < 2; mi++)
#pragma unroll
            for (int ni = 0; ni < 2; ni++)
#pragma unroll
                for (int v = 0; v < 4; v++) acc[mi][ni][v] = 0;

        CP_WAIT0();
        __syncthreads();
#pragma unroll
        for (int c = 0; c < 2; ++c) {
            uint32_t sA = sbase + (uint32_t)(c * STAGE_BYTES);
#pragma unroll
            for (int ks = 0; ks < 4; ++ks) {
                uint32_t a[2][4], b[2][2];
#pragma unroll
                for (int mi = 0; mi < 2; mi++)
                    ldsm4(a[mi], sA + offA + (uint32_t)(mi * 16 * ROWB + ks * 32));
                {
                    uint32_t r[4];
                    ldsm4(r, sA + offB + (uint32_t)(ks * 32));
                    b[0][0] = r[0]; b[0][1] = r[1];
                    b[1][0] = r[2]; b[1][1] = r[3];
                }
#pragma unroll
                for (int mi = 0; mi < 2; mi++)
#pragma unroll
                    for (int ni = 0; ni < 2; ni++)
                        mma_s8(acc[mi][ni], a[mi], b[ni]);
            }
        }
        __syncthreads();                      // stages free for next tile

        int nxt = s_nxt, bi2 = 0, bj2 = 0;
        if (nxt < N_CTAS_T) {
            decode_tile(nxt, bi2, bj2);
            prefetch(bi2 * BTI, bj2 * BTJ);   // DMA overlaps epilogue
        }

        // ---- Epilogue: dv = 2^(acc*rk_i*rk_j + b_i + b_j), masked sums ----
        float bI[4], rkI[4]; int cI[4];
#pragma unroll
        for (int q = 0; q < 4; q++) {
            int rl = R0 + (q >> 1) * 16 + gq + (q & 1) * 8;
            bI[q] = bR[rl]; rkI[q] = rkR[rl]; cI[q] = clR[rl];
        }
        float bJ[4], rkJ[4]; int cJ[4];
#pragma unroll
        for (int q = 0; q < 4; q++) {
            int cl = C0 + (q >> 1) * 8 + tq * 2 + (q & 1);
            bJ[q] = bC[cl]; rkJ[q] = rkC[cl]; cJ[q] = clC[cl];
        }

        float rT[4], rP[4], cT[4], cP[4];
#pragma unroll
        for (int q = 0; q < 4; q++) { rT[q] = rP[q] = cT[q] = cP[q] = 0.f; }

        auto epi = [&](bool chk) {
#pragma unroll
            for (int mi = 0; mi < 2; mi++)
#pragma unroll
                for (int h = 0; h < 2; h++) {
                    int qr = mi * 2 + h;
                    int ig = i0 + R0 + mi * 16 + gq + h * 8;  // global row
                    float bi_ = bI[qr], rki = rkI[qr];
                    int ci = cI[qr];
#pragma unroll
                    for (int ni = 0; ni < 2; ni++)
#pragma unroll
                        for (int w = 0; w < 2; w++) {
                            int qc = ni * 2 + w;
                            float dotf = (float)acc[mi][ni][h * 2 + w];
                            float dv = exp2f(fmaf(dotf, rki * rkJ[qc],
                                                  bi_ + bJ[qc]));
                            if (chk && ig == (j0 + C0 + ni * 8 + tq * 2 + w))
                                dv = 0.f;
                            rT[qr] += dv; cT[qc] += dv;
                            if (ci == cJ[qc]) { rP[qr] += dv; cP[qc] += dv; }
                        }
                }
        };
        if (diag) epi(true); else epi(false);

#pragma unroll
        for (int q = 0; q < 4; q++) {
#pragma unroll
            for (int o = 4; o <= 16; o <<= 1) {
                cT[q] += __shfl_xor_sync(0xffffffffu, cT[q], o);
                cP[q] += __shfl_xor_sync(0xffffffffu, cP[q], o);
            }
        }
        if (lane < 4) {
#pragma unroll
            for (int q = 0; q < 4; q++) {
                int cl = C0 + (q >> 1) * 8 + lane * 2 + (q & 1);
                atomicAdd(&g_pos[j0 + cl], cP[q]);
                atomicAdd(&g_neg[j0 + cl], cT[q] - cP[q]);
            }
        }
#pragma unroll
        for (int q = 0; q < 4; q++) {
#pragma unroll
            for (int o = 1; o <= 2; o <<= 1) {
                rT[q] += __shfl_xor_sync(0xffffffffu, rT[q], o);
                rP[q] += __shfl_xor_sync(0xffffffffu, rP[q], o);
            }
        }
        if (!diag && tq == 0) {
#pragma unroll
            for (int q = 0; q < 4; q++) {
                int rl = R0 + (q >> 1) * 16 + gq + (q & 1) * 8;
                atomicAdd(&g_pos[i0 + rl], rP[q]);
                atomicAdd(&g_neg[i0 + rl], rT[q] - rP[q]);
            }
        }

        // tile completion; last tile's CTA runs the final reduction
        __syncthreads();                      // all atomics issued
        if (tid == 0) {
            __threadfence();
            s_fin = (atomicAdd(&g_done, 1) == N_CTAS_T - 1);
        }
        __syncthreads();                      // s_fin + aux-rewrite guard
        if (s_fin) {
            __threadfence();
            __shared__ float red[16];
            float s = 0.f;
            for (int j = tid; j < N_PTS; j += 512) {
                float num = g_pos[j];
                float den = fmaxf(g_neg[j], EPSF);
                float frac = num / (num + den);
                if (frac >= EPSF) s += logf(frac);
            }
#pragma unroll
            for (int o = 16; o; o >>= 1) s += __shfl_xor_sync(0xffffffffu, s, o);
            if (lane == 0) red[wid] = s;
            __syncthreads();
            if (tid < 16) {
                float v = red[tid];
#pragma unroll
                for (int o = 8; o; o >>= 1) v += __shfl_xor_sync(0xffffu, v, o);
                if (tid == 0) out[0] = -v / (float)N_PTS;
            }
        }

        tile = nxt; bi = bi2; bj = bj2;
    }
}

// ---------------------------------------------------------------------------
extern "C" void kernel_launch(void* const* d_in, const int* in_sizes, int n_in,
                              void* d_out, int out_size) {
    const float* pred = (const float*)d_in[0];
    const void*  tgt  = d_in[1];
    const float* temp = (const float*)d_in[2];

    cudaFuncSetAttribute(tile_kernel,
                         cudaFuncAttributeMaxDynamicSharedMemorySize, SMEM_TOTAL);

    prep_kernel<<<(N_PTS * 32 + 255) / 256, 256>>>(pred, tgt, temp);
    tile_kernel<<<GRID_P, 512, SMEM_TOTAL>>>((float*)d_out);
}

// round 15
// speedup vs baseline: 1.2468x; 1.2468x over previous
#include <cuda_runtime.h>
#include <math.h>
#include <stdint.h>

#define N_PTS 8192
#define D_DIM 256
#define NUM_CLS 64
#define EPSF  1e-10f
#define LOG2E 1.4426950408889634f

#define BT 128                    // tile M = N
#define ROWB 128                  // unpadded row stride (swizzled)
#define CHUNK_BYTES (256 * ROWB)  // 32768: A rows 0-127 + B rows 128-255, one K-half
#define NBUF 3
#define AUX_OFF (NBUF * CHUNK_BYTES)
#define SMEM_TOTAL (AUX_OFF + 6 * BT * 4)
#define N_TILES (N_PTS / BT)      // 64
#define N_CTAS (N_TILES * (N_TILES + 1) / 2)  // 2080
#define GRID_P 296                // persistent CTAs (2 per SM x 148)

__device__ float4   g_aux[N_PTS];           // {b, rk, cls(bits), 0}
__device__ float    g_pos[N_PTS];
__device__ float    g_neg[N_PTS];
__device__ int      g_work;
__device__ int      g_done;
__device__ uint32_t g_q8[N_PTS * (D_DIM / 4)];   // packed int8 rows (256B)

static __device__ __forceinline__ uint32_t smem_u32(const void* p) {
    uint32_t a;
    asm("{ .reg .u64 t; cvta.to.shared.u64 t, %1; cvt.u32.u64 %0, t; }"
        : "=r"(a) : "l"(p));
    return a;
}
static __device__ __forceinline__ void cp16(uint32_t dst, const void* src) {
    asm volatile("cp.async.cg.shared.global [%0], [%1], 16;"
                 :: "r"(dst), "l"(src) : "memory");
}
#define CP_COMMIT() asm volatile("cp.async.commit_group;" ::: "memory")
#define CP_WAIT0()  asm volatile("cp.async.wait_group 0;" ::: "memory")

static __device__ __forceinline__ void ldsm4(uint32_t* r, uint32_t addr) {
    asm volatile("ldmatrix.sync.aligned.m8n8.x4.shared.b16 {%0,%1,%2,%3}, [%4];"
                 : "=r"(r[0]), "=r"(r[1]), "=r"(r[2]), "=r"(r[3]) : "r"(addr));
}
static __device__ __forceinline__ void mma_s8(int* c, const uint32_t* a,
                                              const uint32_t* b) {
    asm volatile(
        "mma.sync.aligned.m16n8k32.row.col.s32.s8.s8.s32 "
        "{%0,%1,%2,%3}, {%4,%5,%6,%7}, {%8,%9}, {%0,%1,%2,%3};"
        : "+r"(c[0]), "+r"(c[1]), "+r"(c[2]), "+r"(c[3])
        : "r"(a[0]), "r"(a[1]), "r"(a[2]), "r"(a[3]), "r"(b[0]), "r"(b[1]));
}
static __device__ __forceinline__ uint32_t pack4(float4 v, float s) {
    int q0 = __float2int_rn(v.x * s), q1 = __float2int_rn(v.y * s);
    int q2 = __float2int_rn(v.z * s), q3 = __float2int_rn(v.w * s);
    return (uint32_t)(q0 & 255) | ((uint32_t)(q1 & 255) << 8) |
           ((uint32_t)(q2 & 255) << 16) | ((uint32_t)(q3 & 255) << 24);
}
static __device__ __forceinline__ void decode_tile(int t, int& bi, int& bj) {
    int b = (int)((129.0f - sqrtf(16641.0f - 8.0f * (float)t)) * 0.5f);
    while ((b + 1) * (129 - (b + 1)) / 2 <= t) ++b;
    while (b * (129 - b) / 2 > t) --b;
    bi = b; bj = b + (t - b * (129 - b) / 2);
}

// ---------------------------------------------------------------------------
// Kernel 1: per-row norm + int8 quantization + temperature-folded constants
// + dtype detect + class load + counter/accumulator reset. One warp per row.
// ---------------------------------------------------------------------------
__global__ void prep_kernel(const float* __restrict__ pred,
                            const void* __restrict__ tgt,
                            const float* __restrict__ tempPtr) {
    int warp = (blockIdx.x * blockDim.x + threadIdx.x) >> 5;
    int lane = threadIdx.x & 31;
    if (warp >= N_PTS) return;

    const long long* t64 = (const long long*)tgt;
    int bad = 0;
#pragma unroll
    for (int q = 0; q < 4; ++q) {
        long long v = t64[lane + 32 * q];
        bad |= (v < 0 || v >= (long long)NUM_CLS);
    }
    bool is64 = (__ballot_sync(0xffffffffu, bad) == 0u);

    const float4* row = (const float4*)(pred + (size_t)warp * D_DIM);
    float4 v0 = row[lane], v1 = row[lane + 32];
    float s = v0.x * v0.x + v0.y * v0.y + v0.z * v0.z + v0.w * v0.w
            + v1.x * v1.x + v1.y * v1.y + v1.z * v1.z + v1.w * v1.w;
    float m = fmaxf(fmaxf(fmaxf(fabsf(v0.x), fabsf(v0.y)),
                          fmaxf(fabsf(v0.z), fabsf(v0.w))),
                    fmaxf(fmaxf(fabsf(v1.x), fabsf(v1.y)),
                          fmaxf(fabsf(v1.z), fabsf(v1.w))));
#pragma unroll
    for (int o = 16; o; o >>= 1) {
        s += __shfl_xor_sync(0xffffffffu, s, o);
        m = fmaxf(m, __shfl_xor_sync(0xffffffffu, m, o));
    }
    float scale = 127.0f / m;                    // m > 0 for gaussian data
    g_q8[warp * 64 + lane]      = pack4(v0, scale);
    g_q8[warp * 64 + 32 + lane] = pack4(v1, scale);
    if (lane == 0) {
        float invT = 1.0f / tempPtr[0];
        float rs   = m * (1.0f / 127.0f);
        int cls    = is64 ? (int)t64[warp] : ((const int*)tgt)[warp];
        g_aux[warp] = make_float4(-s * invT * LOG2E,
                                  rs * sqrtf(2.0f * invT * LOG2E),
                                  __int_as_float(cls), 0.f);
        g_pos[warp] = 0.f;
        g_neg[warp] = 0.f;
        if (warp == 0) { g_work = 0; g_done = 0; }
    }
}

// ---------------------------------------------------------------------------
// Kernel 2: persistent int8 m16n8k32 Gram tiles; 3 rotating chunk-buffers;
// next tile's DMA fully hidden under current mainloop; fused epilogue.
// ---------------------------------------------------------------------------
__global__ __launch_bounds__(256, 2)
void tile_kernel(float* __restrict__ out) {
    extern __shared__ char smc[];
    uint32_t sbase = smem_u32(smc);
    float* bR  = (float*)(smc + AUX_OFF);
    float* bC  = bR + BT;
    float* rkR = bC + BT;
    float* rkC = rkR + BT;
    int*   clR = (int*)(rkC + BT);
    int*   clC = clR + BT;
    __shared__ int s_cur, s_nxt, s_fin;

    int tid  = threadIdx.x;
    int lane = tid & 31, wid = tid >> 5;
    int wm = wid & 1, wn = wid >> 1;              // 2 x 4 warp grid
    int R0 = wm * 64, C0 = wn * 32;
    int gq = lane >> 2, tq = lane & 3;

    // cp.async role: swizzled 16B unit = seg ^ (row&7); row&7 const per thread
    int seg   = tid & 7;
    int rbase = tid >> 3;                         // 0..31
    uint32_t sseg = (uint32_t)((seg ^ (rbase & 7)) << 4);

    auto prefetch_chunk = [&](int buf, int i0, int j0, int k0) {
        uint32_t base = sbase + (uint32_t)buf * CHUNK_BYTES;
#pragma unroll
        for (int i = 0; i < 8; ++i) {
            int row = rbase + 32 * i;             // 0..255
            const char* src = (row < 128)
                ? (const char*)g_q8 + (size_t)(i0 + row) * D_DIM
                : (const char*)g_q8 + (size_t)(j0 + row - 128) * D_DIM;
            cp16(base + (uint32_t)row * ROWB + sseg, src + k0 + seg * 16);
        }
        CP_COMMIT();
    };

    // ldsm swizzled addressing: rx = row&7 = lane&7 in both roles
    uint32_t rx   = (uint32_t)(lane & 7);
    uint32_t rowA = (uint32_t)((R0 + (lane & 15)) * ROWB);
    uint32_t hiA  = (uint32_t)(lane >> 4);
    uint32_t rowB = (uint32_t)((128 + C0 + ((lane >> 4) << 3) + (lane & 7)) * ROWB);
    uint32_t hiB  = (uint32_t)((lane >> 3) & 1);

    if (tid == 0) s_cur = atomicAdd(&g_work, 1);
    __syncthreads();
    int tile = s_cur, bi = 0, bj = 0, rot = 0;
    if (tile < N_CTAS) {
        decode_tile(tile, bi, bj);
        prefetch_chunk(0, bi * BT, bj * BT, 0);
        prefetch_chunk(1, bi * BT, bj * BT, 128);
    }

    while (tile < N_CTAS) {
        int i0 = bi * BT, j0 = bj * BT;
        bool diag = (bi == bj);

        if (tid == 0) s_nxt = atomicAdd(&g_work, 1);
        if (tid < BT) {
            float4 a = g_aux[i0 + tid];
            bR[tid] = a.x; rkR[tid] = a.y; clR[tid] = __float_as_int(a.z);
            float4 b = g_aux[j0 + tid];
            bC[tid] = b.x; rkC[tid] = b.y; clC[tid] = __float_as_int(b.z);
        }

        int acc[4][4][4];
#pragma unroll
        for (int mi = 0; mi < 4; mi++)
#pragma unroll
            for (int ni = 0; ni < 4; ni++)
#pragma unroll
                for (int v = 0; v < 4; v++) acc[mi][ni][v] = 0;

        CP_WAIT0();                               // c0+c1 landed (hidden)
        __syncthreads();                          // + aux/s_nxt visible

        int nxt = s_nxt, bi2 = 0, bj2 = 0;
        bool have_nxt = (nxt < N_CTAS);
        if (have_nxt) decode_tile(nxt, bi2, bj2);
        if (have_nxt)                             // next.c0 -> free buffer
            prefetch_chunk((rot + 2) % 3, bi2 * BT, bj2 * BT, 0);

        auto runchunk = [&](int buf) {
            uint32_t cb = sbase + (uint32_t)buf * CHUNK_BYTES;
#pragma unroll
            for (int ks = 0; ks < 4; ++ks) {
                uint32_t swA = (((2u * ks + hiA) ^ rx) << 4);
                uint32_t swB = (((2u * ks + hiB) ^ rx) << 4);
                uint32_t a[4][4], b[4][2];
#pragma unroll
                for (int mi = 0; mi < 4; mi++)
                    ldsm4(a[mi], cb + rowA + (uint32_t)(mi * 16 * ROWB) + swA);
#pragma unroll
                for (int p = 0; p < 2; p++) {
                    uint32_t r[4];
                    ldsm4(r, cb + rowB + (uint32_t)(p * 16 * ROWB) + swB);
                    b[2 * p][0] = r[0]; b[2 * p][1] = r[1];
                    b[2 * p + 1][0] = r[2]; b[2 * p + 1][1] = r[3];
                }
#pragma unroll
                for (int mi = 0; mi < 4; mi++)
#pragma unroll
                    for (int ni = 0; ni < 4; ni++)
                        mma_s8(acc[mi][ni], a[mi], b[ni]);
            }
        };

        runchunk(rot);                            // chunk 0
        __syncthreads();                          // c0 consumed by all warps
        if (have_nxt)                             // next.c1 -> c0's buffer
            prefetch_chunk(rot, bi2 * BT, bj2 * BT, 128);
        runchunk((rot + 1) % 3);                  // chunk 1

        // ---- Epilogue: dv = 2^(acc*rk_i*rk_j + b_i + b_j), masked sums ----
        float bI[8], rkI[8]; int cI[8];
#pragma unroll
        for (int q = 0; q < 8; q++) {
            int rl = R0 + (q >> 1) * 16 + gq + (q & 1) * 8;
            bI[q] = bR[rl]; rkI[q] = rkR[rl]; cI[q] = clR[rl];
        }
        float bJ[8], rkJ[8]; int cJ[8];
#pragma unroll
        for (int q = 0; q < 8; q++) {
            int cl = C0 + (q >> 1) * 8 + tq * 2 + (q & 1);
            bJ[q] = bC[cl]; rkJ[q] = rkC[cl]; cJ[q] = clC[cl];
        }

        float rT[8], rP[8], cT[8], cP[8];
#pragma unroll
        for (int q = 0; q < 8; q++) { rT[q] = rP[q] = cT[q] = cP[q] = 0.f; }

        auto epi = [&](bool chk) {
#pragma unroll
            for (int mi = 0; mi < 4; mi++)
#pragma unroll
                for (int h = 0; h < 2; h++) {
                    int qr = mi * 2 + h;
                    int rl = R0 + mi * 16 + gq + h * 8;
                    float bi_ = bI[qr], rki = rkI[qr];
                    int ci = cI[qr];
#pragma unroll
                    for (int ni = 0; ni < 4; ni++)
#pragma unroll
                        for (int w = 0; w < 2; w++) {
                            int qc = ni * 2 + w;
                            float dotf = (float)acc[mi][ni][h * 2 + w];
                            float dv = exp2f(fmaf(dotf, rki * rkJ[qc],
                                                  bi_ + bJ[qc]));
                            if (chk && rl == (C0 + ni * 8 + tq * 2 + w))
                                dv = 0.f;
                            rT[qr] += dv; cT[qc] += dv;
                            if (ci == cJ[qc]) { rP[qr] += dv; cP[qc] += dv; }
                        }
                }
        };
        if (diag) epi(true); else epi(false);

#pragma unroll
        for (int q = 0; q < 8; q++) {
#pragma unroll
            for (int o = 4; o <= 16; o <<= 1) {
                cT[q] += __shfl_xor_sync(0xffffffffu, cT[q], o);
                cP[q] += __shfl_xor_sync(0xffffffffu, cP[q], o);
            }
        }
        if (lane < 4) {
#pragma unroll
            for (int q = 0; q < 8; q++) {
                int cl = C0 + (q >> 1) * 8 + lane * 2 + (q & 1);
                atomicAdd(&g_pos[j0 + cl], cP[q]);
                atomicAdd(&g_neg[j0 + cl], cT[q] - cP[q]);
            }
        }
#pragma unroll
        for (int q = 0; q < 8; q++) {
#pragma unroll
            for (int o = 1; o <= 2; o <<= 1) {
                rT[q] += __shfl_xor_sync(0xffffffffu, rT[q], o);
                rP[q] += __shfl_xor_sync(0xffffffffu, rP[q], o);
            }
        }
        if (!diag && tq == 0) {
#pragma unroll
            for (int q = 0; q < 8; q++) {
                int rl = R0 + (q >> 1) * 16 + gq + (q & 1) * 8;
                atomicAdd(&g_pos[i0 + rl], rP[q]);
                atomicAdd(&g_neg[i0 + rl], rT[q] - rP[q]);
            }
        }

        // tile completion; last tile's CTA runs the final reduction
        __syncthreads();                          // all atomics issued
        if (tid == 0) {
            __threadfence();
            s_fin = (atomicAdd(&g_done, 1) == N_CTAS - 1);
        }
        __syncthreads();                          // s_fin + aux-rewrite guard
        if (s_fin) {
            __threadfence();
            __shared__ float red[8];
            float s = 0.f;
            for (int j = tid; j < N_PTS; j += 256) {
                float num = g_pos[j];
                float den = fmaxf(g_neg[j], EPSF);
                float frac = num / (num + den);
                if (frac >= EPSF) s += logf(frac);
            }
#pragma unroll
            for (int o = 16; o; o >>= 1) s += __shfl_xor_sync(0xffffffffu, s, o);
            if (lane == 0) red[wid] = s;
            __syncthreads();
            if (tid < 8) {
                float v = red[tid];
#pragma unroll
                for (int o = 4; o; o >>= 1) v += __shfl_xor_sync(0xffu, v, o);
                if (tid == 0) out[0] = -v / (float)N_PTS;
            }
        }

        tile = nxt; bi = bi2; bj = bj2;
        rot = (rot + 2) % 3;
    }
}

// ---------------------------------------------------------------------------
extern "C" void kernel_launch(void* const* d_in, const int* in_sizes, int n_in,
                              void* d_out, int out_size) {
    const float* pred = (const float*)d_in[0];
    const void*  tgt  = d_in[1];
    const float* temp = (const float*)d_in[2];

    cudaFuncSetAttribute(tile_kernel,
                         cudaFuncAttributeMaxDynamicSharedMemorySize, SMEM_TOTAL);

    prep_kernel<<<(N_PTS * 32 + 255) / 256, 256>>>(pred, tgt, temp);
    tile_kernel<<<GRID_P, 256, SMEM_TOTAL>>>((float*)d_out);
}

// round 16
// speedup vs baseline: 1.3477x; 1.0810x over previous
#include <cuda_runtime.h>
#include <math.h>
#include <stdint.h>

#define N_PTS 8192
#define D_DIM 256
#define NUM_CLS 64
#define EPSF  1e-10f
#define LOG2E 1.4426950408889634f

#define BT 128                    // tile M = N
#define CE 128                    // K chunk in int8 elems = 128 B per row
#define ROWB 144                  // padded row stride in bytes (128 + 16)
#define STAGE_BYTES (256 * ROWB)  // A rows 0-127, B rows 128-255
#define AUX_OFF (2 * STAGE_BYTES)
#define SMEM_TOTAL (AUX_OFF + 6 * BT * 4)
#define N_TILES (N_PTS / BT)      // 64
#define N_CTAS (N_TILES * (N_TILES + 1) / 2)  // 2080
#define GRID_P 296                // persistent CTAs (2 per SM x 148)

__device__ float4   g_aux[N_PTS];           // {b, rk, cls(bits), 0}
__device__ float    g_pos[N_PTS];
__device__ float    g_neg[N_PTS];
__device__ int      g_work;
__device__ int      g_done;
__device__ uint32_t g_q8[N_PTS * (D_DIM / 4)];   // packed int8 rows (256B)

static __device__ __forceinline__ uint32_t smem_u32(const void* p) {
    uint32_t a;
    asm("{ .reg .u64 t; cvta.to.shared.u64 t, %1; cvt.u32.u64 %0, t; }"
        : "=r"(a) : "l"(p));
    return a;
}
static __device__ __forceinline__ float ex2(float x) {
    float y;
    asm("ex2.approx.ftz.f32 %0, %1;" : "=f"(y) : "f"(x));
    return y;
}
static __device__ __forceinline__ void cp16(uint32_t dst, const void* src) {
    asm volatile("cp.async.cg.shared.global [%0], [%1], 16;"
                 :: "r"(dst), "l"(src) : "memory");
}
#define CP_COMMIT() asm volatile("cp.async.commit_group;" ::: "memory")
#define CP_WAIT0()  asm volatile("cp.async.wait_group 0;" ::: "memory")

static __device__ __forceinline__ void ldsm4(uint32_t* r, uint32_t addr) {
    asm volatile("ldmatrix.sync.aligned.m8n8.x4.shared.b16 {%0,%1,%2,%3}, [%4];"
                 : "=r"(r[0]), "=r"(r[1]), "=r"(r[2]), "=r"(r[3]) : "r"(addr));
}
static __device__ __forceinline__ void mma_s8(int* c, const uint32_t* a,
                                              const uint32_t* b) {
    asm volatile(
        "mma.sync.aligned.m16n8k32.row.col.s32.s8.s8.s32 "
        "{%0,%1,%2,%3}, {%4,%5,%6,%7}, {%8,%9}, {%0,%1,%2,%3};"
        : "+r"(c[0]), "+r"(c[1]), "+r"(c[2]), "+r"(c[3])
        : "r"(a[0]), "r"(a[1]), "r"(a[2]), "r"(a[3]), "r"(b[0]), "r"(b[1]));
}
static __device__ __forceinline__ uint32_t pack4(float4 v, float s) {
    int q0 = __float2int_rn(v.x * s), q1 = __float2int_rn(v.y * s);
    int q2 = __float2int_rn(v.z * s), q3 = __float2int_rn(v.w * s);
    return (uint32_t)(q0 & 255) | ((uint32_t)(q1 & 255) << 8) |
           ((uint32_t)(q2 & 255) << 16) | ((uint32_t)(q3 & 255) << 24);
}
static __device__ __forceinline__ void decode_tile(int t, int& bi, int& bj) {
    int b = (int)((129.0f - sqrtf(16641.0f - 8.0f * (float)t)) * 0.5f);
    while ((b + 1) * (129 - (b + 1)) / 2 <= t) ++b;
    while (b * (129 - b) / 2 > t) --b;
    bi = b; bj = b + (t - b * (129 - b) / 2);
}

// ---------------------------------------------------------------------------
// Kernel 1: per-row norm + int8 quantization + temperature-folded constants
// + dtype detect + class load + counter/accumulator reset. One warp per row.
// ---------------------------------------------------------------------------
__global__ void prep_kernel(const float* __restrict__ pred,
                            const void* __restrict__ tgt,
                            const float* __restrict__ tempPtr) {
    int warp = (blockIdx.x * blockDim.x + threadIdx.x) >> 5;
    int lane = threadIdx.x & 31;
    if (warp >= N_PTS) return;

    // dtype scan on first 1KB (L2-resident): int32 data shows values >= 64
    const long long* t64 = (const long long*)tgt;
    int bad = 0;
#pragma unroll
    for (int q = 0; q < 4; ++q) {
        long long v = t64[lane + 32 * q];
        bad |= (v < 0 || v >= (long long)NUM_CLS);
    }
    bool is64 = (__ballot_sync(0xffffffffu, bad) == 0u);

    const float4* row = (const float4*)(pred + (size_t)warp * D_DIM);
    float4 v0 = row[lane], v1 = row[lane + 32];
    float s = v0.x * v0.x + v0.y * v0.y + v0.z * v0.z + v0.w * v0.w
            + v1.x * v1.x + v1.y * v1.y + v1.z * v1.z + v1.w * v1.w;
    float m = fmaxf(fmaxf(fmaxf(fabsf(v0.x), fabsf(v0.y)),
                          fmaxf(fabsf(v0.z), fabsf(v0.w))),
                    fmaxf(fmaxf(fabsf(v1.x), fabsf(v1.y)),
                          fmaxf(fabsf(v1.z), fabsf(v1.w))));
#pragma unroll
    for (int o = 16; o; o >>= 1) {
        s += __shfl_xor_sync(0xffffffffu, s, o);
        m = fmaxf(m, __shfl_xor_sync(0xffffffffu, m, o));
    }
    float scale = 127.0f / m;                    // m > 0 for gaussian data
    g_q8[warp * 64 + lane]      = pack4(v0, scale);
    g_q8[warp * 64 + 32 + lane] = pack4(v1, scale);
    if (lane == 0) {
        float invT = 1.0f / tempPtr[0];
        float rs   = m * (1.0f / 127.0f);
        int cls    = is64 ? (int)t64[warp] : ((const int*)tgt)[warp];
        g_aux[warp] = make_float4(-s * invT * LOG2E,
                                  rs * sqrtf(2.0f * invT * LOG2E),
                                  __int_as_float(cls), 0.f);
        g_pos[warp] = 0.f;
        g_neg[warp] = 0.f;
        if (warp == 0) { g_work = 0; g_done = 0; }
    }
}

// ---------------------------------------------------------------------------
// Kernel 2: persistent int8 m16n8k32 Gram tiles; early work-stealing; one
// wait+barrier mainloop; diag-specialized fused epilogue; folded finalize.
// ---------------------------------------------------------------------------
__global__ __launch_bounds__(256, 2)
void tile_kernel(float* __restrict__ out) {
    extern __shared__ char smc[];
    uint32_t sbase = smem_u32(smc);
    float* bR  = (float*)(smc + AUX_OFF);
    float* bC  = bR + BT;
    float* rkR = bC + BT;
    float* rkC = rkR + BT;
    int*   clR = (int*)(rkC + BT);
    int*   clC = clR + BT;
    __shared__ int s_cur, s_nxt, s_fin;

    int tid  = threadIdx.x;
    int lane = tid & 31, wid = tid >> 5;
    int wm = wid & 1, wn = wid >> 1;              // 2 x 4 warp grid
    int R0 = wm * 64, C0 = wn * 32;
    int gq = lane >> 2, tq = lane & 3;

    int seg = tid & 7;                            // cp.async 16B segment
    int rbase = tid >> 3;

    auto prefetch = [&](int i0, int j0) {
#pragma unroll
        for (int st = 0; st < 2; ++st) {
            uint32_t sdst = sbase + (uint32_t)(st * STAGE_BYTES) + seg * 16u;
            int k0 = st * CE;
#pragma unroll
            for (int i = 0; i < 8; ++i) {
                int row = rbase + 32 * i;         // 0..255
                const char* src = (row < 128)
                    ? (const char*)g_q8 + (size_t)(i0 + row) * D_DIM
                    : (const char*)g_q8 + (size_t)(j0 + row - 128) * D_DIM;
                cp16(sdst + (uint32_t)row * ROWB, src + k0 + seg * 16);
            }
            CP_COMMIT();
        }
    };

    uint32_t offA = (uint32_t)((R0 + (lane & 15)) * ROWB + (lane >> 4) * 16);
    uint32_t offB = (uint32_t)((128 + C0 + (lane >> 4) * 8 + (lane & 7)) * ROWB
                               + ((lane >> 3) & 1) * 16);

    if (tid == 0) s_cur = atomicAdd(&g_work, 1);
    __syncthreads();
    int tile = s_cur, bi = 0, bj = 0;
    if (tile < N_CTAS) {
        decode_tile(tile, bi, bj);
        prefetch(bi * BT, bj * BT);
    }

    while (tile < N_CTAS) {
        int i0 = bi * BT, j0 = bj * BT;
        bool diag = (bi == bj);

        // early steal: atomic latency hides under the mainloop
        if (tid == 0) s_nxt = atomicAdd(&g_work, 1);
        if (tid < BT) {
            float4 a = g_aux[i0 + tid];
            bR[tid] = a.x; rkR[tid] = a.y; clR[tid] = __float_as_int(a.z);
            float4 b = g_aux[j0 + tid];
            bC[tid] = b.x; rkC[tid] = b.y; clC[tid] = __float_as_int(b.z);
        }

        int acc[4][4][4];
#pragma unroll
        for (int mi = 0; mi < 4; mi++)
#pragma unroll
            for (int ni = 0; ni < 4; ni++)
#pragma unroll
                for (int v = 0; v < 4; v++) acc[mi][ni][v] = 0;

        CP_WAIT0();                               // both stages landed
        __syncthreads();                          // + aux/s_nxt visible
#pragma unroll
        for (int c = 0; c < 2; ++c) {
            uint32_t sA = sbase + (uint32_t)(c * STAGE_BYTES);
#pragma unroll
            for (int ks = 0; ks < 4; ++ks) {
                uint32_t a[4][4], b[4][2];
#pragma unroll
                for (int mi = 0; mi < 4; mi++)
                    ldsm4(a[mi], sA + offA + (uint32_t)(mi * 16 * ROWB + ks * 32));
#pragma unroll
                for (int p = 0; p < 2; p++) {
                    uint32_t r[4];
                    ldsm4(r, sA + offB + (uint32_t)(p * 16 * ROWB + ks * 32));
                    b[2 * p][0] = r[0]; b[2 * p][1] = r[1];
                    b[2 * p + 1][0] = r[2]; b[2 * p + 1][1] = r[3];
                }
#pragma unroll
                for (int mi = 0; mi < 4; mi++)
#pragma unroll
                    for (int ni = 0; ni < 4; ni++)
                        mma_s8(acc[mi][ni], a[mi], b[ni]);
            }
        }
        __syncthreads();                          // stages free for next tile

        int nxt = s_nxt, bi2 = 0, bj2 = 0;
        if (nxt < N_CTAS) {
            decode_tile(nxt, bi2, bj2);
            prefetch(bi2 * BT, bj2 * BT);         // DMA overlaps epilogue
        }

        // ---- Epilogue: dv = 2^(acc*rk_i*rk_j + b_i + b_j), masked sums ----
        float bI[8], rkI[8]; int cI[8];
#pragma unroll
        for (int q = 0; q < 8; q++) {
            int rl = R0 + (q >> 1) * 16 + gq + (q & 1) * 8;
            bI[q] = bR[rl]; rkI[q] = rkR[rl]; cI[q] = clR[rl];
        }
        float bJ[8], rkJ[8]; int cJ[8];
#pragma unroll
        for (int q = 0; q < 8; q++) {
            int cl = C0 + (q >> 1) * 8 + tq * 2 + (q & 1);
            bJ[q] = bC[cl]; rkJ[q] = rkC[cl]; cJ[q] = clC[cl];
        }

        float rT[8], rP[8], cT[8], cP[8];
#pragma unroll
        for (int q = 0; q < 8; q++) { rT[q] = rP[q] = cT[q] = cP[q] = 0.f; }

        // branch-specialized body: non-diag tiles (97%) skip the diag check
        auto epi = [&](bool chk) {
#pragma unroll
            for (int mi = 0; mi < 4; mi++)
#pragma unroll
                for (int h = 0; h < 2; h++) {
                    int qr = mi * 2 + h;
                    int rl = R0 + mi * 16 + gq + h * 8;
                    float bi_ = bI[qr], rki = rkI[qr];
                    int ci = cI[qr];
#pragma unroll
                    for (int ni = 0; ni < 4; ni++)
#pragma unroll
                        for (int w = 0; w < 2; w++) {
                            int qc = ni * 2 + w;
                            float dotf = (float)acc[mi][ni][h * 2 + w];
                            float dv = ex2(fmaf(dotf, rki * rkJ[qc],
                                                bi_ + bJ[qc]));
                            if (chk && rl == (C0 + ni * 8 + tq * 2 + w))
                                dv = 0.f;
                            rT[qr] += dv; cT[qc] += dv;
                            if (ci == cJ[qc]) { rP[qr] += dv; cP[qc] += dv; }
                        }
                }
        };
        if (diag) epi(true); else epi(false);

#pragma unroll
        for (int q = 0; q < 8; q++) {
#pragma unroll
            for (int o = 4; o <= 16; o <<= 1) {
                cT[q] += __shfl_xor_sync(0xffffffffu, cT[q], o);
                cP[q] += __shfl_xor_sync(0xffffffffu, cP[q], o);
            }
        }
        if (lane < 4) {
#pragma unroll
            for (int q = 0; q < 8; q++) {
                int cl = C0 + (q >> 1) * 8 + lane * 2 + (q & 1);
                atomicAdd(&g_pos[j0 + cl], cP[q]);
                atomicAdd(&g_neg[j0 + cl], cT[q] - cP[q]);
            }
        }
#pragma unroll
        for (int q = 0; q < 8; q++) {
#pragma unroll
            for (int o = 1; o <= 2; o <<= 1) {
                rT[q] += __shfl_xor_sync(0xffffffffu, rT[q], o);
                rP[q] += __shfl_xor_sync(0xffffffffu, rP[q], o);
            }
        }
        if (!diag && tq == 0) {
#pragma unroll
            for (int q = 0; q < 8; q++) {
                int rl = R0 + (q >> 1) * 16 + gq + (q & 1) * 8;
                atomicAdd(&g_pos[i0 + rl], rP[q]);
                atomicAdd(&g_neg[i0 + rl], rT[q] - rP[q]);
            }
        }

        // tile completion; last tile's CTA runs the final reduction
        __syncthreads();                          // all atomics issued
        if (tid == 0) {
            __threadfence();
            s_fin = (atomicAdd(&g_done, 1) == N_CTAS - 1);
        }
        __syncthreads();                          // s_fin + aux-rewrite guard
        if (s_fin) {
            __threadfence();
            __shared__ float red[8];
            float s = 0.f;
            for (int j = tid; j < N_PTS; j += 256) {
                float num = g_pos[j];
                float den = fmaxf(g_neg[j], EPSF);
                float frac = num / (num + den);
                if (frac >= EPSF) s += logf(frac);
            }
#pragma unroll
            for (int o = 16; o; o >>= 1) s += __shfl_xor_sync(0xffffffffu, s, o);
            if (lane == 0) red[wid] = s;
            __syncthreads();
            if (tid < 8) {
                float v = red[tid];
#pragma unroll
                for (int o = 4; o; o >>= 1) v += __shfl_xor_sync(0xffu, v, o);
                if (tid == 0) out[0] = -v / (float)N_PTS;
            }
        }

        tile = nxt; bi = bi2; bj = bj2;
    }
}

// ---------------------------------------------------------------------------
extern "C" void kernel_launch(void* const* d_in, const int* in_sizes, int n_in,
                              void* d_out, int out_size) {
    const float* pred = (const float*)d_in[0];
    const void*  tgt  = d_in[1];
    const float* temp = (const float*)d_in[2];

    cudaFuncSetAttribute(tile_kernel,
                         cudaFuncAttributeMaxDynamicSharedMemorySize, SMEM_TOTAL);

    prep_kernel<<<(N_PTS * 32 + 255) / 256, 256>>>(pred, tgt, temp);
    tile_kernel<<<GRID_P, 256, SMEM_TOTAL>>>((float*)d_out);
}